// round 6
// baseline (speedup 1.0000x reference)
#include <cuda_runtime.h>
#include <math.h>

#define LTOT    19530
#define BB      64
#define SS      32
#define NROWS   2048
#define NBISECT 40
#define N4      4882        // full float4-column groups per row (4*4882 = 19528)
#define NTILE_B 20          // tiles of 256 float4-groups per row (20*256 >= 4883)
#define NTILES  (BB * NTILE_B)   // 1280
#define PGRID   592         // 148 SMs * 4 blocks

// Scratch (__device__ global: allocation-guard compliant)
__device__ float g_pw[NROWS * 8];   // per-row root powers [row][k] = root^k

// ---------------------------------------------------------------------------
// Kernel 1: per-row per-level squared sums (vectorized, high-MLP) + bisection
// ---------------------------------------------------------------------------
__device__ __forceinline__ void vec_sq_sum(const float* __restrict__ x,
                                           int lo, int hi, int p,
                                           int tid, float& acc) {
    int a = lo + ((((p - lo) % 4) + 4) % 4);      // first idx >= lo with idx%4==p
    if (tid < a - lo) { float v = x[lo + tid]; acc = fmaf(v, v, acc); }
    const int nv = (hi - a) >> 2;
    const float4* __restrict__ xv = (const float4*)(x + a);
    #pragma unroll 8
    for (int i = tid; i < nv; i += 256) {
        float4 v = xv[i];
        acc = fmaf(v.x, v.x, acc);
        acc = fmaf(v.y, v.y, acc);
        acc = fmaf(v.z, v.z, acc);
        acc = fmaf(v.w, v.w, acc);
    }
    const int t0 = a + 4 * nv;
    if (tid < hi - t0) { float v = x[t0 + tid]; acc = fmaf(v, v, acc); }
}

__global__ __launch_bounds__(256, 4) void k_levelsums(const float* __restrict__ sig) {
    const int row = blockIdx.x;
    const int tid = threadIdx.x;
    const float* __restrict__ x = sig + (size_t)row * LTOT;

    float acc[6] = {0.f, 0.f, 0.f, 0.f, 0.f, 0.f};

    const int off[5] = {0, 5, 30, 155, 780};
    #pragma unroll
    for (int k = 0; k < 4; k++)
        for (int i = off[k] + tid; i < off[k + 1]; i += 256) {
            float v = x[i];
            acc[k] = fmaf(v, v, acc[k]);
        }

    // Row byte base = row*78120; 78120 % 16 == 8 -> float4 phase 0 (even) / 2 (odd)
    const int p = (row & 1) ? 2 : 0;
    vec_sq_sum(x, 780,  3905, p, tid, acc[4]);
    vec_sq_sum(x, 3905, LTOT, p, tid, acc[5]);

    __shared__ float sm[8][8];
    __shared__ float totals[8];
    const int lane = tid & 31, w = tid >> 5;
    #pragma unroll
    for (int k = 0; k < 6; k++) {
        float v = acc[k];
        #pragma unroll
        for (int o = 16; o > 0; o >>= 1) v += __shfl_down_sync(0xffffffffu, v, o);
        if (lane == 0) sm[w][k] = v;
    }
    __syncthreads();
    if (w == 0) {
        if (lane < 6) {
            float t = 0.f;
            #pragma unroll
            for (int i = 0; i < 8; i++) t += sm[i][lane];
            totals[lane] = t;
        }
        __syncwarp();
        if (lane == 0) {
            // phi: C=4, a=1 -> phi(x) = 8 - 16/x for x > 4
            float c[7];
            float total = 0.f;
            #pragma unroll
            for (int k = 1; k <= 6; k++) { c[k] = totals[k - 1]; total += c[k]; }
            const float nq  = 1.f + total;
            const float phi = (nq > 4.f) ? (8.f - 16.f / nq) : nq;
            c[0] = 1.f - phi;

            bool fin = true;
            #pragma unroll
            for (int k = 0; k < 7; k++) fin = fin && isfinite(c[k]);

            float lo = 0.f, hi = 2.f;
            #pragma unroll 4
            for (int it = 0; it < NBISECT; it++) {
                const float mid = 0.5f * (lo + hi);
                const float u   = mid * mid;
                float pz = c[6];
                #pragma unroll
                for (int k = 5; k >= 0; k--) pz = fmaf(pz, u, c[k]);
                const bool neg = pz < 0.f;
                lo = neg ? mid : lo;
                hi = neg ? hi  : mid;
            }
            float root = 0.5f * (lo + hi);
            if (!fin) root = 0.f;
            root = fminf(root, 1.f);

            float pw = 1.f;
            g_pw[row * 8 + 0] = 1.f;
            #pragma unroll
            for (int k = 1; k <= 6; k++) { pw *= root; g_pw[row * 8 + k] = pw; }
            g_pw[row * 8 + 7] = 0.f;
        }
    }
}

// ---------------------------------------------------------------------------
// Kernel 2: scale by root^level, mean over S. Persistent grid (no tail wave);
// 4 columns/thread, explicit 8-sample load batches (16 x LDG.64) for MLP.
// ---------------------------------------------------------------------------
__device__ __forceinline__ int level_of(int idx) {
    if (idx < 5)    return 1;
    if (idx < 30)   return 2;
    if (idx < 155)  return 3;
    if (idx < 780)  return 4;
    if (idx < 3905) return 5;
    return 6;
}

__global__ __launch_bounds__(256, 4) void k_scale(const float* __restrict__ sig,
                                                  float* __restrict__ out) {
    __shared__ float spw[SS * 8];
    const float inv = 1.f / (float)SS;

    for (int tile = blockIdx.x; tile < NTILES; tile += gridDim.x) {
        const int b  = tile / NTILE_B;
        const int tt = tile - b * NTILE_B;

        __syncthreads();                     // protect previous tile's spw reads
        spw[threadIdx.x] = g_pw[(size_t)b * SS * 8 + threadIdx.x];
        __syncthreads();

        const int j4 = tt * 256 + (int)threadIdx.x;
        const float* __restrict__ base = sig + (size_t)b * SS * LTOT;

        if (j4 < N4) {
            const int e0 = 4 * j4;
            const int lv0 = level_of(e0);
            const int lv1 = level_of(e0 + 1);
            const int lv2 = level_of(e0 + 2);
            const int lv3 = level_of(e0 + 3);

            float a0 = 0.f, a1 = 0.f, a2 = 0.f, a3 = 0.f;

            #pragma unroll
            for (int sb = 0; sb < SS; sb += 8) {
                // ---- load batch: 16 x LDG.64 before any consumption ----
                float2 u[16];
                #pragma unroll
                for (int t = 0; t < 8; t++) {
                    const float* r = base + (size_t)(sb + t) * LTOT + e0;  // 8B aligned
                    u[2 * t]     = *(const float2*)r;
                    u[2 * t + 1] = *(const float2*)(r + 2);
                }
                #pragma unroll
                for (int t = 0; t < 8; t++) {
                    const int s = sb + t;
                    a0 = fmaf(u[2 * t].x,     spw[s * 8 + lv0], a0);
                    a1 = fmaf(u[2 * t].y,     spw[s * 8 + lv1], a1);
                    a2 = fmaf(u[2 * t + 1].x, spw[s * 8 + lv2], a2);
                    a3 = fmaf(u[2 * t + 1].y, spw[s * 8 + lv3], a3);
                }
            }
            float* o = out + (size_t)b * LTOT + e0;     // 8B aligned
            *(float2*)o       = make_float2(a0 * inv, a1 * inv);
            *(float2*)(o + 2) = make_float2(a2 * inv, a3 * inv);
        } else if (j4 == N4) {
            // tail: elements 19528, 19529 (level 6)
            const int e0 = 4 * N4;
            float a0 = 0.f, a1 = 0.f;
            #pragma unroll 8
            for (int s = 0; s < SS; s++) {
                const float2 v = *(const float2*)(base + (size_t)s * LTOT + e0);
                const float  w = spw[s * 8 + 6];
                a0 = fmaf(v.x, w, a0);
                a1 = fmaf(v.y, w, a1);
            }
            float* o = out + (size_t)b * LTOT + e0;
            *(float2*)o = make_float2(a0 * inv, a1 * inv);
        }
    }
}

// ---------------------------------------------------------------------------
extern "C" void kernel_launch(void* const* d_in, const int* in_sizes, int n_in,
                              void* d_out, int out_size) {
    const float* sig = (const float*)d_in[0];
    float* out = (float*)d_out;

    k_levelsums<<<NROWS, 256>>>(sig);
    k_scale<<<PGRID, 256>>>(sig, out);
}

// round 7
// speedup vs baseline: 1.4191x; 1.4191x over previous
#include <cuda_runtime.h>
#include <math.h>

#define LTOT    19530
#define BB      64
#define SS      32
#define NROWS   2048
#define NBISECT 40
#define N4      4882        // full float4-column groups per row (4*4882 = 19528)
#define NTILE_B 20          // 256-wide float4-group tiles per row (20*256 >= 4883)

// Scratch (__device__ global: allocation-guard compliant)
__device__ float g_pw[NROWS * 8];   // per-row root powers [row][k] = root^k

// ---------------------------------------------------------------------------
// Kernel 1: per-row per-level squared sums (vectorized) + fused bisection
// (exact R3 structure — best measured; reads input FORWARD)
// ---------------------------------------------------------------------------
__device__ __forceinline__ void vec_sq_sum(const float* __restrict__ x,
                                           int lo, int hi, int p,
                                           int tid, float& acc) {
    int a = lo + ((((p - lo) % 4) + 4) % 4);      // first idx >= lo with idx%4==p
    if (tid < a - lo) { float v = x[lo + tid]; acc = fmaf(v, v, acc); }
    const int nv = (hi - a) >> 2;
    const float4* __restrict__ xv = (const float4*)(x + a);
    #pragma unroll 4
    for (int i = tid; i < nv; i += 256) {
        float4 v = xv[i];
        acc = fmaf(v.x, v.x, acc);
        acc = fmaf(v.y, v.y, acc);
        acc = fmaf(v.z, v.z, acc);
        acc = fmaf(v.w, v.w, acc);
    }
    const int t0 = a + 4 * nv;
    if (tid < hi - t0) { float v = x[t0 + tid]; acc = fmaf(v, v, acc); }
}

__global__ __launch_bounds__(256) void k_levelsums(const float* __restrict__ sig) {
    const int row = blockIdx.x;
    const int tid = threadIdx.x;
    const float* __restrict__ x = sig + (size_t)row * LTOT;

    float acc[6] = {0.f, 0.f, 0.f, 0.f, 0.f, 0.f};

    const int off[5] = {0, 5, 30, 155, 780};
    #pragma unroll
    for (int k = 0; k < 4; k++)
        for (int i = off[k] + tid; i < off[k + 1]; i += 256) {
            float v = x[i];
            acc[k] = fmaf(v, v, acc[k]);
        }

    // Row byte base = row*78120; 78120 % 16 == 8 -> float4 phase 0 (even) / 2 (odd)
    const int p = (row & 1) ? 2 : 0;
    vec_sq_sum(x, 780,  3905, p, tid, acc[4]);
    vec_sq_sum(x, 3905, LTOT, p, tid, acc[5]);

    __shared__ float sm[8][8];
    __shared__ float totals[8];
    const int lane = tid & 31, w = tid >> 5;
    #pragma unroll
    for (int k = 0; k < 6; k++) {
        float v = acc[k];
        #pragma unroll
        for (int o = 16; o > 0; o >>= 1) v += __shfl_down_sync(0xffffffffu, v, o);
        if (lane == 0) sm[w][k] = v;
    }
    __syncthreads();
    if (w == 0) {
        if (lane < 6) {
            float t = 0.f;
            #pragma unroll
            for (int i = 0; i < 8; i++) t += sm[i][lane];
            totals[lane] = t;
        }
        __syncwarp();
        if (lane == 0) {
            // phi: C=4, a=1 -> phi(x) = 8 - 16/x for x > 4
            float c[7];
            float total = 0.f;
            #pragma unroll
            for (int k = 1; k <= 6; k++) { c[k] = totals[k - 1]; total += c[k]; }
            const float nq  = 1.f + total;
            const float phi = (nq > 4.f) ? (8.f - 16.f / nq) : nq;
            c[0] = 1.f - phi;

            bool fin = true;
            #pragma unroll
            for (int k = 0; k < 7; k++) fin = fin && isfinite(c[k]);

            float lo = 0.f, hi = 2.f;
            #pragma unroll 4
            for (int it = 0; it < NBISECT; it++) {
                const float mid = 0.5f * (lo + hi);
                const float u   = mid * mid;
                float pz = c[6];
                #pragma unroll
                for (int k = 5; k >= 0; k--) pz = fmaf(pz, u, c[k]);
                const bool neg = pz < 0.f;
                lo = neg ? mid : lo;
                hi = neg ? hi  : mid;
            }
            float root = 0.5f * (lo + hi);
            if (!fin) root = 0.f;
            root = fminf(root, 1.f);

            float pw = 1.f;
            g_pw[row * 8 + 0] = 1.f;
            #pragma unroll
            for (int k = 1; k <= 6; k++) { pw *= root; g_pw[row * 8 + k] = pw; }
            g_pw[row * 8 + 7] = 0.f;
        }
    }
}

// ---------------------------------------------------------------------------
// Kernel 2: scale by root^level, mean over S (R5 batched-load version) but
// walking the input in REVERSE address order for cross-kernel L2 reuse:
// it starts where k_levelsums just finished (hot in L2) and finishes at the
// low end, which is where the next replay's k_levelsums begins.
// ---------------------------------------------------------------------------
__device__ __forceinline__ int level_of(int idx) {
    if (idx < 5)    return 1;
    if (idx < 30)   return 2;
    if (idx < 155)  return 3;
    if (idx < 780)  return 4;
    if (idx < 3905) return 5;
    return 6;
}

__global__ __launch_bounds__(256, 4) void k_scale(const float* __restrict__ sig,
                                                  float* __restrict__ out) {
    // Reverse mapping: blockIdx 0 -> highest (b, tile); blocks launch in
    // roughly ascending blockIdx order, so data is visited high->low address.
    const int rtile = (BB * NTILE_B - 1) - (int)blockIdx.x;
    const int b  = rtile / NTILE_B;
    const int tt = rtile - b * NTILE_B;

    __shared__ float spw[SS * 8];
    spw[threadIdx.x] = g_pw[(size_t)b * SS * 8 + threadIdx.x];
    __syncthreads();

    // within tile, reverse threads too so the whole walk is descending
    const int j4 = tt * 256 + (255 - (int)threadIdx.x);
    if (j4 > N4) return;

    const float* __restrict__ base = sig + (size_t)b * SS * LTOT;
    const float inv = 1.f / (float)SS;

    if (j4 < N4) {
        const int e0 = 4 * j4;
        const int lv0 = level_of(e0);
        const int lv1 = level_of(e0 + 1);
        const int lv2 = level_of(e0 + 2);
        const int lv3 = level_of(e0 + 3);

        float a0 = 0.f, a1 = 0.f, a2 = 0.f, a3 = 0.f;

        #pragma unroll
        for (int sb = 0; sb < SS; sb += 8) {
            // ---- load batch: 16 x LDG.64 issued before any consumption ----
            float2 u[16];
            #pragma unroll
            for (int t = 0; t < 8; t++) {
                const float* r = base + (size_t)(sb + t) * LTOT + e0;  // 8B aligned
                u[2 * t]     = *(const float2*)r;
                u[2 * t + 1] = *(const float2*)(r + 2);
            }
            #pragma unroll
            for (int t = 0; t < 8; t++) {
                const int s = sb + t;
                a0 = fmaf(u[2 * t].x,     spw[s * 8 + lv0], a0);
                a1 = fmaf(u[2 * t].y,     spw[s * 8 + lv1], a1);
                a2 = fmaf(u[2 * t + 1].x, spw[s * 8 + lv2], a2);
                a3 = fmaf(u[2 * t + 1].y, spw[s * 8 + lv3], a3);
            }
        }
        float* o = out + (size_t)b * LTOT + e0;     // 8B aligned
        *(float2*)o       = make_float2(a0 * inv, a1 * inv);
        *(float2*)(o + 2) = make_float2(a2 * inv, a3 * inv);
    } else {
        // tail: elements 19528, 19529 (level 6)
        const int e0 = 4 * N4;
        float a0 = 0.f, a1 = 0.f;
        #pragma unroll 8
        for (int s = 0; s < SS; s++) {
            const float2 v = *(const float2*)(base + (size_t)s * LTOT + e0);
            const float  w = spw[s * 8 + 6];
            a0 = fmaf(v.x, w, a0);
            a1 = fmaf(v.y, w, a1);
        }
        float* o = out + (size_t)b * LTOT + e0;
        *(float2*)o = make_float2(a0 * inv, a1 * inv);
    }
}

// ---------------------------------------------------------------------------
extern "C" void kernel_launch(void* const* d_in, const int* in_sizes, int n_in,
                              void* d_out, int out_size) {
    const float* sig = (const float*)d_in[0];
    float* out = (float*)d_out;

    k_levelsums<<<NROWS, 256>>>(sig);
    dim3 g2(BB * NTILE_B, 1);   // 1280 blocks, reversed mapping inside
    k_scale<<<g2, 256>>>(sig, out);
}

// round 9
// speedup vs baseline: 1.4836x; 1.0454x over previous
#include <cuda_runtime.h>
#include <math.h>

#define LTOT    19530
#define BB      64
#define SS      32
#define NROWS   2048
#define NBISECT 40
#define N4      4882        // full float4-column groups per row (4*4882 = 19528)
#define NTILE_B 20          // 256-wide float4-group tiles per row
#define NTILES  (BB * NTILE_B)

// Scratch (__device__ global: allocation-guard compliant)
__device__ float g_pw[NROWS * 8];   // per-row root powers [row][k] = root^k

// ---------------------------------------------------------------------------
// Kernel 1: per-row per-level squared sums + fused bisection (R3/R7 — frozen)
// ---------------------------------------------------------------------------
__device__ __forceinline__ void vec_sq_sum(const float* __restrict__ x,
                                           int lo, int hi, int p,
                                           int tid, float& acc) {
    int a = lo + ((((p - lo) % 4) + 4) % 4);
    if (tid < a - lo) { float v = x[lo + tid]; acc = fmaf(v, v, acc); }
    const int nv = (hi - a) >> 2;
    const float4* __restrict__ xv = (const float4*)(x + a);
    #pragma unroll 4
    for (int i = tid; i < nv; i += 256) {
        float4 v = xv[i];
        acc = fmaf(v.x, v.x, acc);
        acc = fmaf(v.y, v.y, acc);
        acc = fmaf(v.z, v.z, acc);
        acc = fmaf(v.w, v.w, acc);
    }
    const int t0 = a + 4 * nv;
    if (tid < hi - t0) { float v = x[t0 + tid]; acc = fmaf(v, v, acc); }
}

__global__ __launch_bounds__(256) void k_levelsums(const float* __restrict__ sig) {
    const int row = blockIdx.x;
    const int tid = threadIdx.x;
    const float* __restrict__ x = sig + (size_t)row * LTOT;

    float acc[6] = {0.f, 0.f, 0.f, 0.f, 0.f, 0.f};

    const int off[5] = {0, 5, 30, 155, 780};
    #pragma unroll
    for (int k = 0; k < 4; k++)
        for (int i = off[k] + tid; i < off[k + 1]; i += 256) {
            float v = x[i];
            acc[k] = fmaf(v, v, acc[k]);
        }

    const int p = (row & 1) ? 2 : 0;
    vec_sq_sum(x, 780,  3905, p, tid, acc[4]);
    vec_sq_sum(x, 3905, LTOT, p, tid, acc[5]);

    __shared__ float sm[8][8];
    __shared__ float totals[8];
    const int lane = tid & 31, w = tid >> 5;
    #pragma unroll
    for (int k = 0; k < 6; k++) {
        float v = acc[k];
        #pragma unroll
        for (int o = 16; o > 0; o >>= 1) v += __shfl_down_sync(0xffffffffu, v, o);
        if (lane == 0) sm[w][k] = v;
    }
    __syncthreads();
    if (w == 0) {
        if (lane < 6) {
            float t = 0.f;
            #pragma unroll
            for (int i = 0; i < 8; i++) t += sm[i][lane];
            totals[lane] = t;
        }
        __syncwarp();
        if (lane == 0) {
            float c[7];
            float total = 0.f;
            #pragma unroll
            for (int k = 1; k <= 6; k++) { c[k] = totals[k - 1]; total += c[k]; }
            const float nq  = 1.f + total;
            const float phi = (nq > 4.f) ? (8.f - 16.f / nq) : nq;   // C=4, a=1
            c[0] = 1.f - phi;

            bool fin = true;
            #pragma unroll
            for (int k = 0; k < 7; k++) fin = fin && isfinite(c[k]);

            float lo = 0.f, hi = 2.f;
            #pragma unroll 4
            for (int it = 0; it < NBISECT; it++) {
                const float mid = 0.5f * (lo + hi);
                const float u   = mid * mid;
                float pz = c[6];
                #pragma unroll
                for (int k = 5; k >= 0; k--) pz = fmaf(pz, u, c[k]);
                const bool neg = pz < 0.f;
                lo = neg ? mid : lo;
                hi = neg ? hi  : mid;
            }
            float root = 0.5f * (lo + hi);
            if (!fin) root = 0.f;
            root = fminf(root, 1.f);

            float pw = 1.f;
            g_pw[row * 8 + 0] = 1.f;
            #pragma unroll
            for (int k = 1; k <= 6; k++) { pw *= root; g_pw[row * 8 + k] = pw; }
            g_pw[row * 8 + 7] = 0.f;
        }
    }
}

// ---------------------------------------------------------------------------
// Kernel 2: scale + mean over S. All-LDG.128: odd rows load shifted (+2 cols,
// 16B aligned there); ownership fixed by one smem shift-add. Tail thread sums
// EVEN samples only (odd come via shift-add) — fixes R8 double count.
// Reverse tile order preserved for cross-kernel L2 reuse.
// ---------------------------------------------------------------------------
__device__ __forceinline__ int level_of(int idx) {
    if (idx < 5)    return 1;
    if (idx < 30)   return 2;
    if (idx < 155)  return 3;
    if (idx < 780)  return 4;
    if (idx < 3905) return 5;
    return 6;
}

__global__ __launch_bounds__(256, 4) void k_scale(const float* __restrict__ sig,
                                                  float* __restrict__ out) {
    const int rtile = (NTILES - 1) - (int)blockIdx.x;   // high tiles first
    const int b  = rtile / NTILE_B;
    const int tt = rtile - b * NTILE_B;
    const int tid = threadIdx.x;

    __shared__ float spw[SS * 8];
    __shared__ float sh[4 * 256 + 4];   // shifted odd-row sums, by column offset

    spw[tid] = g_pw[(size_t)b * SS * 8 + tid];
    __syncthreads();

    const int j4 = tt * 256 + tid;
    const int e0 = 4 * j4;
    const bool full = (j4 < N4);
    const bool tail = (j4 == N4);

    const float* __restrict__ base = sig + (size_t)b * SS * LTOT;
    const float inv = 1.f / (float)SS;

    float a0 = 0.f, a1 = 0.f, a2 = 0.f, a3 = 0.f;       // cols e0..e0+3
    float c0 = 0.f, c1 = 0.f, c2 = 0.f, c3 = 0.f;       // odd rows, cols e0+2..e0+5
    float h0 = 0.f, h1 = 0.f;                           // block halo: first 2 cols, odd rows

    if (full) {
        const int lv0 = level_of(e0);
        const int lv1 = level_of(e0 + 1);
        const int lv2 = level_of(e0 + 2);
        const int lv3 = level_of(e0 + 3);
        const int lv4 = level_of(e0 + 4);
        const int lv5 = level_of(e0 + 5);

        #pragma unroll
        for (int sb = 0; sb < SS; sb += 8) {
            // 8 x LDG.128, all 16B-aligned, front-batched
            float4 ue[4], uo[4];
            #pragma unroll
            for (int t = 0; t < 4; t++)
                ue[t] = *(const float4*)(base + (size_t)(sb + 2 * t) * LTOT + e0);
            #pragma unroll
            for (int t = 0; t < 4; t++)
                uo[t] = *(const float4*)(base + (size_t)(sb + 2 * t + 1) * LTOT + e0 + 2);
            #pragma unroll
            for (int t = 0; t < 4; t++) {
                const int se = sb + 2 * t, so = se + 1;
                a0 = fmaf(ue[t].x, spw[se * 8 + lv0], a0);
                a1 = fmaf(ue[t].y, spw[se * 8 + lv1], a1);
                a2 = fmaf(ue[t].z, spw[se * 8 + lv2], a2);
                a3 = fmaf(ue[t].w, spw[se * 8 + lv3], a3);
                c0 = fmaf(uo[t].x, spw[so * 8 + lv2], c0);
                c1 = fmaf(uo[t].y, spw[so * 8 + lv3], c1);
                c2 = fmaf(uo[t].z, spw[so * 8 + lv4], c2);
                c3 = fmaf(uo[t].w, spw[so * 8 + lv5], c3);
            }
        }
        if (tid == 0) {
            // halo: odd rows' first two columns of this block's tile
            #pragma unroll
            for (int s = 1; s < SS; s += 2) {
                const float2 v = *(const float2*)(base + (size_t)s * LTOT + e0);
                h0 = fmaf(v.x, spw[s * 8 + lv0], h0);
                h1 = fmaf(v.y, spw[s * 8 + lv1], h1);
            }
        }
    } else if (tail) {
        // cols 19528, 19529 (level 6): EVEN rows only — odd rows come from
        // the previous thread's shifted c2/c3 via sh (fixes double count).
        #pragma unroll
        for (int s = 0; s < SS; s += 2) {
            const float2 v = *(const float2*)(base + (size_t)s * LTOT + e0);
            const float  w6 = spw[s * 8 + 6];
            a0 = fmaf(v.x, w6, a0);
            a1 = fmaf(v.y, w6, a1);
        }
    }

    // column-offset shift: thread t's c_i sit at column offset 4t+2+i
    if (tid == 0) { sh[0] = h0; sh[1] = h1; }
    sh[4 * tid + 2] = full ? c0 : 0.f;
    sh[4 * tid + 3] = full ? c1 : 0.f;
    sh[4 * tid + 4] = full ? c2 : 0.f;
    sh[4 * tid + 5] = full ? c3 : 0.f;
    __syncthreads();

    if (full) {
        float* o = out + (size_t)b * LTOT + e0;   // 8B aligned
        *(float2*)o       = make_float2((a0 + sh[4 * tid])     * inv,
                                        (a1 + sh[4 * tid + 1]) * inv);
        *(float2*)(o + 2) = make_float2((a2 + sh[4 * tid + 2]) * inv,
                                        (a3 + sh[4 * tid + 3]) * inv);
    } else if (tail) {
        float* o = out + (size_t)b * LTOT + e0;
        *(float2*)o = make_float2((a0 + sh[4 * tid])     * inv,
                                  (a1 + sh[4 * tid + 1]) * inv);
    }
}

// ---------------------------------------------------------------------------
extern "C" void kernel_launch(void* const* d_in, const int* in_sizes, int n_in,
                              void* d_out, int out_size) {
    const float* sig = (const float*)d_in[0];
    float* out = (float*)d_out;

    k_levelsums<<<NROWS, 256>>>(sig);
    k_scale<<<NTILES, 256>>>(sig, out);
}